// round 2
// baseline (speedup 1.0000x reference)
#include <cuda_runtime.h>

typedef unsigned long long u64;
#define FULLMASK 0xffffffffu

// ---------------------------------------------------------------------------
// Precomputed per-ring tables (row-independent):
//   g_cs[r][i][lane] = (cos, sin) of angle at k = 32*lane + 31 - i
//                      (lane 0, i==31 holds (c0, s0) for the wrap epilogue)
//   g_cp[r][i][lane] = c_k * P(i),  P(i) = prod_{i'<i} (-s_{k(i')})  (fixup coeff)
//   g_A [r][lane]    = full within-lane product of (-s)  (lane 0: 31 factors, k=31..1)
// Layout is lane-minor so LDS accesses are conflict-free.
// ---------------------------------------------------------------------------
__device__ float2 g_cs[8][32][32];
__device__ float  g_cp[8][32][32];
__device__ float  g_A[8][32];

static __device__ __forceinline__ u64 pk2(float lo, float hi) {
    u64 r; asm("mov.b64 %0, {%1, %2};" : "=l"(r) : "f"(lo), "f"(hi)); return r;
}
static __device__ __forceinline__ u64 bc2(float v) { return pk2(v, v); }
static __device__ __forceinline__ void up2(u64 v, float& lo, float& hi) {
    asm("mov.b64 {%0, %1}, %2;" : "=f"(lo), "=f"(hi) : "l"(v));
}
static __device__ __forceinline__ u64 f2fma(u64 a, u64 b, u64 c) {
    u64 d; asm("fma.rn.f32x2 %0, %1, %2, %3;" : "=l"(d) : "l"(a), "l"(b), "l"(c)); return d;
}
static __device__ __forceinline__ u64 f2mul(u64 a, u64 b) {
    u64 d; asm("mul.rn.f32x2 %0, %1, %2;" : "=l"(d) : "l"(a), "l"(b)); return d;
}

// ---------------------------------------------------------------------------
// Table precompute: one thread per (ring, lane). Trivial cost.
// Rings 0..3 = enc blocks 0..3, rings 4..7 = dec blocks 0..3.
// ---------------------------------------------------------------------------
__global__ void precompute_tables(const float* __restrict__ ae,
                                  const float* __restrict__ ad) {
    int t = threadIdx.x;
    if (t >= 256) return;
    int r = t >> 5, lane = t & 31;
    const float* ang = (r < 4) ? (ae + r * 1024) : (ad + (r - 4) * 1024);
    float P = 1.0f;
    for (int i = 0; i < 32; i++) {
        int k = lane * 32 + 31 - i;
        float a = ang[k];
        float c = cosf(a), s = sinf(a);
        g_cs[r][i][lane] = make_float2(c, s);
        if (lane == 0 && i == 31) {
            // k == 0: real (c0,s0) stored for the wrap epilogue; no chain step.
            g_cp[r][i][lane] = 0.0f;
        } else {
            g_cp[r][i][lane] = c * P;
            P *= -s;
        }
    }
    g_A[r][lane] = P;
}

// ---------------------------------------------------------------------------
// One ring applied to a warp's 2 packed rows held in registers.
// Lane l owns columns [32l, 32l+32) as f32x2 (rowA in lo, rowB in hi).
// ---------------------------------------------------------------------------
static __device__ __forceinline__ void apply_ring(
    u64 (&d)[32], int r, int lane,
    const float2* __restrict__ s_cs,
    const float*  __restrict__ s_cp,
    const float*  __restrict__ s_A)
{
    u64 x0 = __shfl_sync(FULLMASK, d[0], 0);          // x[:,0] for both rows
    const float2* cs = s_cs + r * 1024 + lane;        // stride 32 per i, lane-minor
    const float*  cp = s_cp + r * 1024 + lane;

    u64 v   = 0ull;                                   // zero-init carry (f32x2 0,0)
    u64 bnd = 0ull;                                   // boundary output (slot 32l+32)
    float c0 = 0.0f, s0 = 0.0f;

    // Main pass (descending k): y0[k+1] = c*v + s*x_k ; v = -s*v + c*x_k
    #pragma unroll
    for (int i = 0; i < 31; i++) {
        float2 csv = cs[i * 32];
        u64 c2 = bc2(csv.x);
        u64 xk = d[31 - i];
        u64 y0 = f2fma(c2, v, f2mul(bc2(csv.y), xk));
        if (i == 0) bnd = y0; else d[32 - i] = y0;
        v = f2fma(bc2(-csv.y), v, f2mul(c2, xk));
    }
    {   // i == 31 (k = 32*lane). Lane 0: k==0 is the special epilogue -> stash c0,s0.
        float2 csv = cs[31 * 32];
        if (lane == 0) {
            c0 = csv.x; s0 = csv.y;
        } else {
            u64 c2 = bc2(csv.x);
            u64 xk = d[0];
            d[1] = f2fma(c2, v, f2mul(bc2(csv.y), xk));
            v = f2fma(bc2(-csv.y), v, f2mul(c2, xk));
        }
    }

    // Suffix scan of affine maps F_l(v) = A_l v + B_l over lanes (high -> low).
    float A    = s_A[r * 32 + lane];
    float Aown = A;
    u64   q    = v;       // zero-init final carry of this lane
    u64   B    = v;
    #pragma unroll
    for (int dd = 1; dd < 32; dd <<= 1) {
        float Ao = __shfl_down_sync(FULLMASK, A, dd);
        u64   Bo = __shfl_down_sync(FULLMASK, B, dd);
        if (lane + dd < 32) {
            B = f2fma(bc2(A), Bo, B);
            A = A * Ao;
        }
    }
    float SA = __shfl_down_sync(FULLMASK, A, 1);
    u64   SB = __shfl_down_sync(FULLMASK, B, 1);
    // True incoming carry for this lane's segment; lane 31 seeds with x0.
    u64 V = (lane == 31) ? x0 : f2fma(bc2(SA), x0, SB);

    // Fixups: y = y0 + CP * V   (CP row-independent, from table)
    bnd = f2fma(bc2(cp[0]), V, bnd);
    #pragma unroll
    for (int i = 1; i < 32; i++) {
        d[32 - i] = f2fma(bc2(cp[i * 32]), V, d[32 - i]);
    }

    // Boundary pass: lane l's top output belongs to lane l+1's lowest slot.
    // Lane 31's boundary is p = s_{n-1} x_{n-1} + c_{n-1} x_0, used by lane 0.
    u64 p2  = __shfl_sync(FULLMASK, bnd, 31);
    u64 rec = __shfl_up_sync(FULLMASK, bnd, 1);
    if (lane > 0) {
        d[0] = rec;
    } else {
        u64 vf = f2fma(bc2(Aown), V, q);              // carry_1
        d[0] = f2fma(bc2(-s0), vf, f2mul(bc2(c0), p2));   // y0 = c0 p - s0 carry1
        d[1] = f2fma(bc2(c0),  vf, f2mul(bc2(s0), p2));   // y1 = s0 p + c0 carry1
    }
}

// ---------------------------------------------------------------------------
// Fused kernel: load 2 rows/warp -> 4 enc rings -> blend -> store bottleneck
// -> 4 dec rings -> store out. Tables staged in dynamic smem (97 KB).
// ---------------------------------------------------------------------------
extern "C" __global__ void __launch_bounds__(256, 2)
enc_dec_kernel(const float* __restrict__ x,
               const float* __restrict__ hw,
               const float* __restrict__ hs,
               float* __restrict__ out, int B)
{
    extern __shared__ unsigned char smem_raw[];
    float2* s_cs = (float2*)smem_raw;                         // 64 KB
    float*  s_cp = (float*)(smem_raw + 65536);                // 32 KB
    float*  s_A  = (float*)(smem_raw + 65536 + 32768);        // 1 KB
    {
        const float4* g1 = (const float4*)(const void*)g_cs;
        float4* s1 = (float4*)(void*)s_cs;
        for (int i = threadIdx.x; i < 4096; i += 256) s1[i] = g1[i];
        const float4* g2 = (const float4*)(const void*)g_cp;
        float4* s2 = (float4*)(void*)s_cp;
        for (int i = threadIdx.x; i < 2048; i += 256) s2[i] = g2[i];
        const float4* g3 = (const float4*)(const void*)g_A;
        float4* s3 = (float4*)(void*)s_A;
        for (int i = threadIdx.x; i < 64; i += 256) s3[i] = g3[i];
    }
    __syncthreads();

    int warp = threadIdx.x >> 5;
    int lane = threadIdx.x & 31;
    long long rowA = ((long long)blockIdx.x * 8 + warp) * 2;
    const float* pA = x + rowA * 1024 + lane * 32;

    // Each lane owns one 128B line per row: fully-consumed coalesced-by-line loads.
    u64 d[32];
    #pragma unroll
    for (int t = 0; t < 8; t++) {
        float4 a = *(const float4*)(pA + 4 * t);
        float4 b = *(const float4*)(pA + 1024 + 4 * t);
        d[4 * t + 0] = pk2(a.x, b.x);
        d[4 * t + 1] = pk2(a.y, b.y);
        d[4 * t + 2] = pk2(a.z, b.z);
        d[4 * t + 3] = pk2(a.w, b.w);
    }

    #pragma unroll 1
    for (int r = 0; r < 4; r++) apply_ring(d, r, lane, s_cs, s_cp, s_A);

    // Bottleneck blend: (1-w)*b + w*h, w = sigmoid(hidden_weight[0])
    float hwv = __ldg(hw);
    float w = 1.0f / (1.0f + expf(-hwv));
    u64 w2 = bc2(w), iw2 = bc2(1.0f - w);
    const float* ph = hs + lane * 32;
    float* ob = out + rowA * 1024 + lane * 32;
    float* oo = out + (long long)B * 1024 + rowA * 1024 + lane * 32;

    #pragma unroll
    for (int t = 0; t < 8; t++) {
        float4 h4 = *(const float4*)(ph + 4 * t);
        d[4 * t + 0] = f2fma(iw2, d[4 * t + 0], f2mul(w2, bc2(h4.x)));
        d[4 * t + 1] = f2fma(iw2, d[4 * t + 1], f2mul(w2, bc2(h4.y)));
        d[4 * t + 2] = f2fma(iw2, d[4 * t + 2], f2mul(w2, bc2(h4.z)));
        d[4 * t + 3] = f2fma(iw2, d[4 * t + 3], f2mul(w2, bc2(h4.w)));
        float4 oa, obv;
        up2(d[4 * t + 0], oa.x, obv.x);
        up2(d[4 * t + 1], oa.y, obv.y);
        up2(d[4 * t + 2], oa.z, obv.z);
        up2(d[4 * t + 3], oa.w, obv.w);
        *(float4*)(ob + 4 * t) = oa;
        *(float4*)(ob + 1024 + 4 * t) = obv;
    }

    #pragma unroll 1
    for (int r = 4; r < 8; r++) apply_ring(d, r, lane, s_cs, s_cp, s_A);

    #pragma unroll
    for (int t = 0; t < 8; t++) {
        float4 oa, obv;
        up2(d[4 * t + 0], oa.x, obv.x);
        up2(d[4 * t + 1], oa.y, obv.y);
        up2(d[4 * t + 2], oa.z, obv.z);
        up2(d[4 * t + 3], oa.w, obv.w);
        *(float4*)(oo + 4 * t) = oa;
        *(float4*)(oo + 1024 + 4 * t) = obv;
    }
}

// ---------------------------------------------------------------------------
extern "C" void kernel_launch(void* const* d_in, const int* in_sizes, int n_in,
                              void* d_out, int out_size) {
    const float* x  = (const float*)d_in[0];
    const float* ae = (const float*)d_in[1];
    const float* ad = (const float*)d_in[2];
    const float* hw = (const float*)d_in[3];
    const float* hs = (const float*)d_in[4];
    float* out = (float*)d_out;

    int B = in_sizes[0] / 1024;          // 8192
    const int smem_bytes = 65536 + 32768 + 1024;

    precompute_tables<<<1, 256>>>(ae, ad);

    cudaFuncSetAttribute(enc_dec_kernel,
                         cudaFuncAttributeMaxDynamicSharedMemorySize, smem_bytes);
    int blocks = B / 16;                 // 16 rows per block (8 warps x 2 rows)
    enc_dec_kernel<<<blocks, 256, smem_bytes>>>(x, hw, hs, out, B);
}